// round 16
// baseline (speedup 1.0000x reference)
#include <cuda_runtime.h>
#include <cuda_fp16.h>
#include <stdint.h>
#include <math.h>

#define SEQ 2048
#define DM  1024
#define DFF 4096
#define DIN 2048
#define NH  16
#define XPN 96
#define DST 16
#define KSPL 8

// ---------------- fp32 scratch ---------------------------------------------
__device__ float g_x1  [SEQ*DM];
__device__ float g_xin [SEQ*DIN];
__device__ float g_xdbc[SEQ*XPN];
__device__ float g_Bm  [SEQ*DST];
__device__ float g_Cm  [SEQ*DST];
__device__ float g_H   [SEQ*DST];
__device__ float g_sv  [SEQ];
__device__ float g_mt  [SEQ*DM];
__device__ float g_x2  [SEQ*DM];
__device__ float g_M   [256];
__device__ float g_M64 [256];
__device__ float g_xpp [KSPL*SEQ*128];  // split-K partials for xp gemm
__device__ float g_pp  [2*SEQ*DM];      // split-K2 partials (N=1024 gemms)
__device__ float g_qkvb[3*DM];          // concatenated q|k|v bias

// ---------------- fp16 hi/lo split scratch (activations) -------------------
__device__ __align__(256) __half g_lnh[SEQ*DM],  g_lnl[SEQ*DM];
__device__ __align__(256) __half g_qkvh[SEQ*3*DM], g_qkvl[SEQ*3*DM];
__device__ __align__(256) __half g_aoh[SEQ*DM],  g_aol[SEQ*DM];
__device__ __align__(256) __half g_xch[SEQ*DIN], g_xcl[SEQ*DIN];
__device__ __align__(256) __half g_yh [SEQ*DIN], g_yl [SEQ*DIN];
__device__ __align__(256) __half g_ffh[SEQ*DFF], g_ffl[SEQ*DFF];
// ---------------- fp16 hi/lo split scratch (weights) -----------------------
__device__ __align__(256) __half g_wqkvh[3*DM*DM], g_wqkvl[3*DM*DM];
__device__ __align__(256) __half g_woh[DM*DM],   g_wol[DM*DM];
__device__ __align__(256) __half g_inh[DIN*DM],  g_inl[DIN*DM];
__device__ __align__(256) __half g_xph[128*DIN], g_xpl[128*DIN];
__device__ __align__(256) __half g_oth[DM*DIN],  g_otl[DM*DIN];
__device__ __align__(256) __half g_f1h[DFF*DM],  g_f1l[DFF*DM];
__device__ __align__(256) __half g_f2h[DM*DFF],  g_f2l[DM*DFF];

// ---------------- helpers ---------------------------------------------------
__device__ __forceinline__ void split_h(float v, __half& h, __half& l) {
    h = __float2half_rn(v);
    l = __float2half_rn(v - __half2float(h));
}
__device__ __forceinline__ void sp2(float a, float b, uint32_t& hi, uint32_t& lo) {
    __half ha = __float2half_rn(a), hb = __float2half_rn(b);
    __half la = __float2half_rn(a - __half2float(ha));
    __half lb = __float2half_rn(b - __half2float(hb));
    hi = ((uint32_t)__half_as_ushort(hb) << 16) | __half_as_ushort(ha);
    lo = ((uint32_t)__half_as_ushort(lb) << 16) | __half_as_ushort(la);
}
__device__ __forceinline__ void mma_f16(float* d, const uint32_t* a,
                                        const uint32_t* b, const float* c) {
    asm volatile(
        "mma.sync.aligned.m16n8k16.row.col.f32.f16.f16.f32 "
        "{%0,%1,%2,%3}, {%4,%5,%6,%7}, {%8,%9}, {%10,%11,%12,%13};\n"
        : "=f"(d[0]), "=f"(d[1]), "=f"(d[2]), "=f"(d[3])
        : "r"(a[0]), "r"(a[1]), "r"(a[2]), "r"(a[3]),
          "r"(b[0]), "r"(b[1]),
          "f"(c[0]), "f"(c[1]), "f"(c[2]), "f"(c[3]));
}
__device__ __forceinline__ void ldsm4(uint32_t addr, uint32_t* r) {
    asm volatile("ldmatrix.sync.aligned.m8n8.x4.shared.b16 {%0,%1,%2,%3}, [%4];"
                 : "=r"(r[0]), "=r"(r[1]), "=r"(r[2]), "=r"(r[3]) : "r"(addr));
}
__device__ __forceinline__ void ldsm4t(uint32_t addr, uint32_t* r) {
    asm volatile("ldmatrix.sync.aligned.m8n8.x4.trans.shared.b16 {%0,%1,%2,%3}, [%4];"
                 : "=r"(r[0]), "=r"(r[1]), "=r"(r[2]), "=r"(r[3]) : "r"(addr));
}
__device__ __forceinline__ void cp16(uint32_t s, const void* g) {
    asm volatile("cp.async.cg.shared.global [%0], [%1], 16;\n"
                 :: "r"(s), "l"(g) : "memory");
}

// ---------------- weight split: W (N,K) -> hi/lo (Npad,K), zero padding ----
__global__ void wsplit_k(const float* __restrict__ W,
                         __half* __restrict__ h, __half* __restrict__ l,
                         int N, int K, int Npad)
{
    int idx = blockIdx.x * blockDim.x + threadIdx.x;
    if (idx >= Npad * K) return;
    int row = idx / K;
    float v = (row < N) ? W[idx] : 0.f;
    split_h(v, h[idx], l[idx]);
}

// ---------------- concat q|k|v biases --------------------------------------
__global__ void catb_k(const float* __restrict__ bq, const float* __restrict__ bk,
                       const float* __restrict__ bv)
{
    int i = blockIdx.x * blockDim.x + threadIdx.x;
    if (i >= 3*DM) return;
    g_qkvb[i] = (i < DM) ? bq[i] : (i < 2*DM) ? bk[i - DM] : bv[i - 2*DM];
}

// ------- split-fp16 GEMM: 3 products hh+hl+lh, ldmatrix + m16n8k16 ---------
// A,B as fp16 hi/lo arrays. A: (M,K), B: (Npad,K) row-major.
// OM: 0 = fp32 out (+bias)(+res), 1 = (GELU+) split out (+bias), 2 = split-K.
// Tile 128x128, BK=32, 256 thr = 2x4 warps; warp 64x32 via 4x4 m16n8k16.
#define AWH 5120        // halves per array (128*40)
template<int OM, bool GELU, bool RES>
__global__ void __launch_bounds__(256) gemm2(
    const __half* __restrict__ Ah, const __half* __restrict__ Al,
    const __half* __restrict__ Bh, const __half* __restrict__ Bl,
    const float* __restrict__ bias, const float* __restrict__ res,
    float* __restrict__ C, __half* __restrict__ Ch, __half* __restrict__ Cl,
    int M, int N, int K)
{
    extern __shared__ __half smh[];   // [2 buf][Ah,Al,Bh,Bl][AWH]
    const int tid = threadIdx.x;
    const int warp = tid >> 5, lane = tid & 31;
    const int g = lane >> 2, tig = lane & 3;
    const int wm = warp >> 2, wn = warp & 3;
    const int bm = blockIdx.y * 128, bn = blockIdx.x * 128;

    int kb = 0, klen = K;
    if (OM == 2) { klen = K / gridDim.z; kb = blockIdx.z * klen; }
    const int nk = klen >> 5;

    const uint32_t sbase = (uint32_t)__cvta_generic_to_shared(smh);

    const int rsel = (lane & 7) + ((lane >> 3) & 1) * 8;
    const int csel = ((lane >> 4) & 1) * 8;

    float acc[4][4][4];
    #pragma unroll
    for (int i = 0; i < 4; i++)
        #pragma unroll
        for (int j = 0; j < 4; j++)
            #pragma unroll
            for (int r = 0; r < 4; r++) acc[i][j][r] = 0.f;

    auto issue = [&](int kt, int buf) {
        const int k0 = kb + (kt << 5);
        #pragma unroll
        for (int u = 0; u < 2; u++) {
            const int id = tid + (u << 8);
            const int row = id >> 2, ch = (id & 3) << 3;
            const uint32_t so = sbase + (row * 40 + ch) * 2;
            const size_t ga = (size_t)(bm + row) * K + k0 + ch;
            const size_t gb = (size_t)(bn + row) * K + k0 + ch;
            cp16(so + (buf*4 + 0) * (AWH*2), Ah + ga);
            cp16(so + (buf*4 + 1) * (AWH*2), Al + ga);
            cp16(so + (buf*4 + 2) * (AWH*2), Bh + gb);
            cp16(so + (buf*4 + 3) * (AWH*2), Bl + gb);
        }
        asm volatile("cp.async.commit_group;\n" ::: "memory");
    };

    issue(0, 0);

    for (int kt = 0; kt < nk; kt++) {
        const int buf = kt & 1;
        if (kt + 1 < nk) {
            issue(kt + 1, buf ^ 1);
            asm volatile("cp.async.wait_group 1;\n" ::: "memory");
        } else {
            asm volatile("cp.async.wait_group 0;\n" ::: "memory");
        }
        __syncthreads();
        const uint32_t bAh = sbase + (buf*4 + 0) * (AWH*2);
        const uint32_t bAl = sbase + (buf*4 + 1) * (AWH*2);
        const uint32_t bBh = sbase + (buf*4 + 2) * (AWH*2);
        const uint32_t bBl = sbase + (buf*4 + 3) * (AWH*2);
        #pragma unroll
        for (int ks = 0; ks < 2; ks++) {
            uint32_t ah[4][4], al[4][4], bh[4][2], bl[4][2];
            #pragma unroll
            for (int i = 0; i < 4; i++) {
                const uint32_t ao = ((wm*64 + i*16 + rsel) * 40 + ks*16 + csel) * 2;
                ldsm4(bAh + ao, ah[i]);
                ldsm4(bAl + ao, al[i]);
            }
            #pragma unroll
            for (int jj = 0; jj < 2; jj++) {
                uint32_t t0[4], t1[4];
                const uint32_t bo = ((wn*32 + jj*16 + rsel) * 40 + ks*16 + csel) * 2;
                ldsm4(bBh + bo, t0);
                ldsm4(bBl + bo, t1);
                bh[2*jj][0]   = t0[0]; bh[2*jj][1]   = t0[2];
                bh[2*jj+1][0] = t0[1]; bh[2*jj+1][1] = t0[3];
                bl[2*jj][0]   = t1[0]; bl[2*jj][1]   = t1[2];
                bl[2*jj+1][0] = t1[1]; bl[2*jj+1][1] = t1[3];
            }
            #pragma unroll
            for (int i = 0; i < 4; i++)
                #pragma unroll
                for (int j = 0; j < 4; j++) {
                    mma_f16(acc[i][j], ah[i], bh[j], acc[i][j]);
                    mma_f16(acc[i][j], ah[i], bl[j], acc[i][j]);
                    mma_f16(acc[i][j], al[i], bh[j], acc[i][j]);
                }
        }
        __syncthreads();
    }

    // epilogue
    #pragma unroll
    for (int i = 0; i < 4; i++) {
        const int r0 = bm + wm*64 + i*16 + g;
        const int r1 = r0 + 8;
        #pragma unroll
        for (int j = 0; j < 4; j++) {
            const int c = bn + wn*32 + j*8 + 2*tig;
            float v0 = acc[i][j][0], v1 = acc[i][j][1];
            float v2 = acc[i][j][2], v3 = acc[i][j][3];
            if (OM == 2) {
                float* Cp = C + (size_t)blockIdx.z * M * N;
                *(float2*)&Cp[(size_t)r0*N + c] = make_float2(v0, v1);
                *(float2*)&Cp[(size_t)r1*N + c] = make_float2(v2, v3);
            } else if (c < N) {
                if (bias) {
                    const float b0 = bias[c], b1 = bias[c+1];
                    v0 += b0; v1 += b1; v2 += b0; v3 += b1;
                }
                if (RES) {
                    v0 += res[(size_t)r0*N + c];
                    v1 += res[(size_t)r0*N + c + 1];
                    v2 += res[(size_t)r1*N + c];
                    v3 += res[(size_t)r1*N + c + 1];
                }
                if (GELU) {
                    #define GLU(u) (0.5f*(u)*(1.f + tanhf(0.7978845608f*((u) + 0.044715f*(u)*(u)*(u)))))
                    v0 = GLU(v0); v1 = GLU(v1); v2 = GLU(v2); v3 = GLU(v3);
                    #undef GLU
                }
                if (OM == 0) {
                    *(float2*)&C[(size_t)r0*N + c] = make_float2(v0, v1);
                    *(float2*)&C[(size_t)r1*N + c] = make_float2(v2, v3);
                } else {   // OM==1: split output
                    split_h(v0, Ch[(size_t)r0*N + c],     Cl[(size_t)r0*N + c]);
                    split_h(v1, Ch[(size_t)r0*N + c + 1], Cl[(size_t)r0*N + c + 1]);
                    split_h(v2, Ch[(size_t)r1*N + c],     Cl[(size_t)r1*N + c]);
                    split_h(v3, Ch[(size_t)r1*N + c + 1], Cl[(size_t)r1*N + c + 1]);
                }
            }
        }
    }
}
#define GEMM_SMEM (2 * 4 * AWH * 2)   // 81920 bytes

// ---------------- reduce split-K2 partials (N=1024 gemms) ------------------
template<bool RES>
__global__ void reduce2_k(const float* __restrict__ P, const float* __restrict__ bias,
                          const float* __restrict__ res, float* __restrict__ C)
{
    int idx = blockIdx.x * blockDim.x + threadIdx.x;
    if (idx >= SEQ * DM) return;
    float v = P[idx] + P[idx + SEQ*DM] + bias[idx & (DM-1)];
    if (RES) v += res[idx];
    C[idx] = v;
}

// ---------------- reduce split-K partials for xp gemm ----------------------
__global__ void reduce_xp(const float* __restrict__ xpb)
{
    int idx = blockIdx.x * blockDim.x + threadIdx.x;
    if (idx >= SEQ * XPN) return;
    int m = idx / XPN, n = idx - m * XPN;
    float s = xpb[n];
    #pragma unroll
    for (int z = 0; z < KSPL; z++)
        s += g_xpp[((size_t)z * SEQ + m) * 128 + n];
    g_xdbc[idx] = s;
}

// ---------------- MMA flash attention (split fp16, fp32 softmax) -----------
#define ALD 72
#define ATTN_SMEM (6 * 64 * ALD * 2)
__global__ void __launch_bounds__(128) attn_k(
    const __half* __restrict__ QKVh, const __half* __restrict__ QKVl,
    __half* __restrict__ Oh, __half* __restrict__ Ol)
{
    extern __shared__ __half sa[];
    const uint32_t sb = (uint32_t)__cvta_generic_to_shared(sa);
    const uint32_t bQh = sb;
    const uint32_t bQl = bQh + 64*ALD*2;
    const uint32_t bKh = bQl + 64*ALD*2;
    const uint32_t bKl = bKh + 64*ALD*2;
    const uint32_t bVh = bKl + 64*ALD*2;
    const uint32_t bVl = bVh + 64*ALD*2;

    const int tid = threadIdx.x;
    const int warp = tid >> 5, lane = tid & 31;
    const int g = lane >> 2, tig = lane & 3;
    const int q0 = blockIdx.x * 64;
    const int cb = blockIdx.y * 64;
    const int LDM = 3*DM;

    const int rsel = (lane & 7) + ((lane >> 3) & 1) * 8;
    const int csel = ((lane >> 4) & 1) * 8;

    #pragma unroll
    for (int u = 0; u < 4; u++) {
        const int id = tid + u*128;
        const int r = id >> 3, ch = (id & 7) * 8;
        const uint32_t so = (r * ALD + ch) * 2;
        const size_t go = (size_t)(q0 + r) * LDM + cb + ch;
        cp16(bQh + so, QKVh + go);
        cp16(bQl + so, QKVl + go);
    }
    asm volatile("cp.async.commit_group;\n" ::: "memory");

    float m_i[2] = {-1e30f, -1e30f};
    float l_i[2] = {0.f, 0.f};
    float oacc[8][4];
    #pragma unroll
    for (int j = 0; j < 8; j++)
        #pragma unroll
        for (int r = 0; r < 4; r++) oacc[j][r] = 0.f;

    for (int kt = 0; kt < SEQ/64; kt++) {
        #pragma unroll
        for (int u = 0; u < 4; u++) {
            const int id = tid + u*128;
            const int r = id >> 3, ch = (id & 7) * 8;
            const uint32_t so = (r * ALD + ch) * 2;
            const size_t gk = (size_t)(kt*64 + r) * LDM + DM + cb + ch;
            cp16(bKh + so, QKVh + gk);
            cp16(bKl + so, QKVl + gk);
            cp16(bVh + so, QKVh + gk + DM);
            cp16(bVl + so, QKVl + gk + DM);
        }
        asm volatile("cp.async.commit_group;\n" ::: "memory");
        asm volatile("cp.async.wait_group 0;\n" ::: "memory");
        __syncthreads();

        float s[8][4];
        #pragma unroll
        for (int j = 0; j < 8; j++)
            #pragma unroll
            for (int r = 0; r < 4; r++) s[j][r] = 0.f;
        #pragma unroll
        for (int ks = 0; ks < 4; ks++) {
            uint32_t qh[4], ql[4];
            const uint32_t ao = ((warp*16 + rsel) * ALD + ks*16 + csel) * 2;
            ldsm4(bQh + ao, qh);
            ldsm4(bQl + ao, ql);
            #pragma unroll
            for (int jj = 0; jj < 4; jj++) {
                uint32_t t0[4], t1[4];
                const uint32_t bo = ((jj*16 + rsel) * ALD + ks*16 + csel) * 2;
                ldsm4(bKh + bo, t0);
                ldsm4(bKl + bo, t1);
                uint32_t bhA[2] = {t0[0], t0[2]}, bhB[2] = {t0[1], t0[3]};
                uint32_t blA[2] = {t1[0], t1[2]}, blB[2] = {t1[1], t1[3]};
                mma_f16(s[2*jj],   qh, bhA, s[2*jj]);
                mma_f16(s[2*jj],   qh, blA, s[2*jj]);
                mma_f16(s[2*jj],   ql, bhA, s[2*jj]);
                mma_f16(s[2*jj+1], qh, bhB, s[2*jj+1]);
                mma_f16(s[2*jj+1], qh, blB, s[2*jj+1]);
                mma_f16(s[2*jj+1], ql, bhB, s[2*jj+1]);
            }
        }
        float mx0 = -1e30f, mx1 = -1e30f;
        #pragma unroll
        for (int j = 0; j < 8; j++) {
            s[j][0] *= 0.125f; s[j][1] *= 0.125f;
            s[j][2] *= 0.125f; s[j][3] *= 0.125f;
            mx0 = fmaxf(mx0, fmaxf(s[j][0], s[j][1]));
            mx1 = fmaxf(mx1, fmaxf(s[j][2], s[j][3]));
        }
        mx0 = fmaxf(mx0, __shfl_xor_sync(0xffffffffu, mx0, 1));
        mx0 = fmaxf(mx0, __shfl_xor_sync(0xffffffffu, mx0, 2));
        mx1 = fmaxf(mx1, __shfl_xor_sync(0xffffffffu, mx1, 1));
        mx1 = fmaxf(mx1, __shfl_xor_sync(0xffffffffu, mx1, 2));
        const float mn0 = fmaxf(m_i[0], mx0), mn1 = fmaxf(m_i[1], mx1);
        const float sc0 = __expf(m_i[0] - mn0), sc1 = __expf(m_i[1] - mn1);
        float sum0 = 0.f, sum1 = 0.f;
        #pragma unroll
        for (int j = 0; j < 8; j++) {
            s[j][0] = __expf(s[j][0] - mn0); sum0 += s[j][0];
            s[j][1] = __expf(s[j][1] - mn0); sum0 += s[j][1];
            s[j][2] = __expf(s[j][2] - mn1); sum1 += s[j][2];
            s[j][3] = __expf(s[j][3] - mn1); sum1 += s[j][3];
        }
        sum0 += __shfl_xor_sync(0xffffffffu, sum0, 1);
        sum0 += __shfl_xor_sync(0xffffffffu, sum0, 2);
        sum1 += __shfl_xor_sync(0xffffffffu, sum1, 1);
        sum1 += __shfl_xor_sync(0xffffffffu, sum1, 2);
        l_i[0] = l_i[0]*sc0 + sum0;
        l_i[1] = l_i[1]*sc1 + sum1;
        m_i[0] = mn0; m_i[1] = mn1;
        #pragma unroll
        for (int j = 0; j < 8; j++) {
            oacc[j][0] *= sc0; oacc[j][1] *= sc0;
            oacc[j][2] *= sc1; oacc[j][3] *= sc1;
        }
        #pragma unroll
        for (int ks2 = 0; ks2 < 4; ks2++) {
            uint32_t ph[4], pl[4];
            sp2(s[2*ks2][0],   s[2*ks2][1],   ph[0], pl[0]);
            sp2(s[2*ks2][2],   s[2*ks2][3],   ph[1], pl[1]);
            sp2(s[2*ks2+1][0], s[2*ks2+1][1], ph[2], pl[2]);
            sp2(s[2*ks2+1][2], s[2*ks2+1][3], ph[3], pl[3]);
            #pragma unroll
            for (int jj = 0; jj < 4; jj++) {
                uint32_t t0[4], t1[4];
                const uint32_t vo = ((ks2*16 + rsel) * ALD + jj*16 + csel) * 2;
                ldsm4t(bVh + vo, t0);
                ldsm4t(bVl + vo, t1);
                uint32_t vA[2] = {t0[0], t0[1]}, vB[2] = {t0[2], t0[3]};
                uint32_t wA[2] = {t1[0], t1[1]}, wB[2] = {t1[2], t1[3]};
                mma_f16(oacc[2*jj],   ph, vA, oacc[2*jj]);
                mma_f16(oacc[2*jj],   ph, wA, oacc[2*jj]);
                mma_f16(oacc[2*jj],   pl, vA, oacc[2*jj]);
                mma_f16(oacc[2*jj+1], ph, vB, oacc[2*jj+1]);
                mma_f16(oacc[2*jj+1], ph, wB, oacc[2*jj+1]);
                mma_f16(oacc[2*jj+1], pl, vB, oacc[2*jj+1]);
            }
        }
        __syncthreads();
    }
    const float li0 = 1.f / l_i[0], li1 = 1.f / l_i[1];
    const int row0 = q0 + warp*16 + g, row1 = row0 + 8;
    #pragma unroll
    for (int j = 0; j < 8; j++) {
        const int col = cb + j*8 + 2*tig;
        split_h(oacc[j][0]*li0, Oh[(size_t)row0*DM + col],   Ol[(size_t)row0*DM + col]);
        split_h(oacc[j][1]*li0, Oh[(size_t)row0*DM + col+1], Ol[(size_t)row0*DM + col+1]);
        split_h(oacc[j][2]*li1, Oh[(size_t)row1*DM + col],   Ol[(size_t)row1*DM + col]);
        split_h(oacc[j][3]*li1, Oh[(size_t)row1*DM + col+1], Ol[(size_t)row1*DM + col+1]);
    }
}

// ---------------- LayerNorm ------------------------------------------------
template<bool AFF, bool RES, bool WF, bool WS>
__global__ void __launch_bounds__(256) ln_k(
    const float* __restrict__ X, const float* __restrict__ g,
    const float* __restrict__ b, const float* __restrict__ res,
    float* __restrict__ Y, __half* __restrict__ Yh, __half* __restrict__ Yl)
{
    const int row = blockIdx.x;
    const float* x = X + (size_t)row * DM;
    const int tid = threadIdx.x;
    float v[4];
    float s = 0.f;
    #pragma unroll
    for (int u = 0; u < 4; u++) { v[u] = x[tid + 256*u]; s += v[u]; }
    __shared__ float red[8];
    __shared__ float stat[2];
    #pragma unroll
    for (int off = 16; off; off >>= 1) s += __shfl_xor_sync(0xffffffffu, s, off);
    if ((tid & 31) == 0) red[tid >> 5] = s;
    __syncthreads();
    if (tid == 0) {
        float t = 0.f;
        for (int k2 = 0; k2 < 8; k2++) t += red[k2];
        stat[0] = t * (1.f/1024.f);
    }
    __syncthreads();
    float mu = stat[0];
    float q = 0.f;
    #pragma unroll
    for (int u = 0; u < 4; u++) { float d = v[u] - mu; q += d*d; }
    #pragma unroll
    for (int off = 16; off; off >>= 1) q += __shfl_xor_sync(0xffffffffu, q, off);
    if ((tid & 31) == 0) red[tid >> 5] = q;
    __syncthreads();
    if (tid == 0) {
        float t = 0.f;
        for (int k2 = 0; k2 < 8; k2++) t += red[k2];
        stat[1] = rsqrtf(t * (1.f/1024.f) + 1e-5f);
    }
    __syncthreads();
    float rstd = stat[1];
    #pragma unroll
    for (int u = 0; u < 4; u++) {
        int c = tid + 256*u;
        float o = (v[u] - mu) * rstd;
        if (AFF) o = o * g[c] + b[c];
        if (RES) o += res[(size_t)row * DM + c];
        const size_t idx = (size_t)row * DM + c;
        if (WF) Y[idx] = o;
        if (WS) split_h(o, Yh[idx], Yl[idx]);
    }
}

// ---------------- fused double LayerNorm (mamba): LN(LN(x)*g+b), split out --
__global__ void __launch_bounds__(256) ln2_k(
    const float* __restrict__ X, const float* __restrict__ g,
    const float* __restrict__ b, __half* __restrict__ Yh,
    __half* __restrict__ Yl)
{
    const int row = blockIdx.x;
    const float* x = X + (size_t)row * DM;
    const int tid = threadIdx.x;
    __shared__ float red[8];
    __shared__ float stat[2];
    float v[4];

    // pass 1: LN with affine
    float s = 0.f;
    #pragma unroll
    for (int u = 0; u < 4; u++) { v[u] = x[tid + 256*u]; s += v[u]; }
    #pragma unroll
    for (int off = 16; off; off >>= 1) s += __shfl_xor_sync(0xffffffffu, s, off);
    if ((tid & 31) == 0) red[tid >> 5] = s;
    __syncthreads();
    if (tid == 0) {
        float t = 0.f;
        for (int k2 = 0; k2 < 8; k2++) t += red[k2];
        stat[0] = t * (1.f/1024.f);
    }
    __syncthreads();
    float mu = stat[0];
    float q = 0.f;
    #pragma unroll
    for (int u = 0; u < 4; u++) { float d = v[u] - mu; q += d*d; }
    #pragma unroll
    for (int off = 16; off; off >>= 1) q += __shfl_xor_sync(0xffffffffu, q, off);
    if ((tid & 31) == 0) red[tid >> 5] = q;
    __syncthreads();
    if (tid == 0) {
        float t = 0.f;
        for (int k2 = 0; k2 < 8; k2++) t += red[k2];
        stat[1] = rsqrtf(t * (1.f/1024.f) + 1e-5f);
    }
    __syncthreads();
    float rstd = stat[1];
    #pragma unroll
    for (int u = 0; u < 4; u++) {
        int c = tid + 256*u;
        v[u] = (v[u] - mu) * rstd * g[c] + b[c];
    }
    __syncthreads();

    // pass 2: plain LN of v, split output
    s = 0.f;
    #pragma unroll
    for (int u = 0; u < 4; u++) s += v[u];
    #pragma unroll
    for (int off = 16; off; off >>= 1) s += __shfl_xor_sync(0xffffffffu, s, off);
    if ((tid & 31) == 0) red[tid >> 5] = s;
    __syncthreads();
    if (tid == 0) {
        float t = 0.f;
        for (int k2 = 0; k2 < 8; k2++) t += red[k2];
        stat[0] = t * (1.f/1024.f);
    }
    __syncthreads();
    mu = stat[0];
    q = 0.f;
    #pragma unroll
    for (int u = 0; u < 4; u++) { float d = v[u] - mu; q += d*d; }
    #pragma unroll
    for (int off = 16; off; off >>= 1) q += __shfl_xor_sync(0xffffffffu, q, off);
    if ((tid & 31) == 0) red[tid >> 5] = q;
    __syncthreads();
    if (tid == 0) {
        float t = 0.f;
        for (int k2 = 0; k2 < 8; k2++) t += red[k2];
        stat[1] = rsqrtf(t * (1.f/1024.f) + 1e-5f);
    }
    __syncthreads();
    rstd = stat[1];
    #pragma unroll
    for (int u = 0; u < 4; u++) {
        int c = tid + 256*u;
        const size_t idx = (size_t)row * DM + c;
        split_h((v[u] - mu) * rstd, Yh[idx], Yl[idx]);
    }
}

// ---------------- depthwise causal conv1d (k=4), split output --------------
__global__ void conv_k(const float* __restrict__ cw, const float* __restrict__ cb)
{
    int idx = blockIdx.x * blockDim.x + threadIdx.x;
    if (idx >= SEQ * DIN) return;
    int t = idx >> 11, c = idx & (DIN - 1);
    float acc = cb[c];
    #pragma unroll
    for (int k = 0; k < 4; k++) {
        int ts = t + k - 3;
        if (ts >= 0) acc = fmaf(cw[c*4 + k], g_xin[(size_t)ts * DIN + c], acc);
    }
    split_h(acc, g_xch[idx], g_xcl[idx]);
}

// ---------------- B/C extraction: LN96 then LN16 ---------------------------
__global__ void bc_k()
{
    const int row = blockIdx.x;
    const int lane = threadIdx.x;
    const float* xr = g_xdbc + (size_t)row * XPN;
    float a0 = xr[lane], a1 = xr[lane + 32], a2 = xr[lane + 64];
    float s = a0 + a1 + a2;
    #pragma unroll
    for (int off = 16; off; off >>= 1) s += __shfl_xor_sync(0xffffffffu, s, off);
    float mu = s * (1.f/96.f);
    float d0 = a0-mu, d1 = a1-mu, d2 = a2-mu;
    float q = d0*d0 + d1*d1 + d2*d2;
    #pragma unroll
    for (int off = 16; off; off >>= 1) q += __shfl_xor_sync(0xffffffffu, q, off);
    float rstd = rsqrtf(q * (1.f/96.f) + 1e-5f);
    float vv = d2 * rstd;
    float hs = vv;
    #pragma unroll
    for (int off = 8; off; off >>= 1) hs += __shfl_xor_sync(0xffffffffu, hs, off);
    float m16 = hs * (1.f/16.f);
    float dd = vv - m16;
    float qq = dd * dd;
    #pragma unroll
    for (int off = 8; off; off >>= 1) qq += __shfl_xor_sync(0xffffffffu, qq, off);
    float o = dd * rsqrtf(qq * (1.f/16.f) + 1e-5f);
    if (lane < 16) g_Bm[row*16 + lane] = o;
    else           g_Cm[row*16 + lane - 16] = o;
}

// ---------------- build M and M^64 -----------------------------------------
__global__ void __launch_bounds__(256) buildM_k(const float* __restrict__ A)
{
    __shared__ float sred[256], sP[256];
    const int t = threadIdx.x;
    const int i = t >> 4, j = t & 15;
    float la = logf(fabsf(A[j*16 + i]) + 1e-8f);
    sred[t] = la;
    __syncthreads();
    for (int off = 128; off > 0; off >>= 1) {
        if (t < off) sred[t] = fminf(sred[t], sred[t + off]);
        __syncthreads();
    }
    float mn = sred[0];
    float Mv = expf(mn - la);
    Mv = fminf(fmaxf(Mv, 1e-4f), 1e4f);
    g_M[t] = Mv;
    sP[t] = Mv;
    __syncthreads();
    for (int it = 0; it < 6; ++it) {
        float acc = 0.f;
        #pragma unroll
        for (int k = 0; k < 16; k++) acc = fmaf(sP[i*16 + k], sP[k*16 + j], acc);
        __syncthreads();
        sP[t] = acc;
        __syncthreads();
    }
    g_M64[t] = sP[t];
}

// ---------------- chunked parallel scan ------------------------------------
__global__ void __launch_bounds__(1024) scan_k()
{
    __shared__ float sM[256], sM64[256], sE[32*16], sS[32*16];
    const int tid = threadIdx.x;
    if (tid < 256) { sM[tid] = g_M[tid]; sM64[tid] = g_M64[tid]; }
    __syncthreads();
    const int w = tid >> 5, lane = tid & 31;
    float mrow[16];
    #pragma unroll
    for (int j = 0; j < 16; j++) mrow[j] = (lane < 16) ? sM[lane*16 + j] : 0.f;
    const int t0 = w * 64;
    float h = 0.f;
    for (int k = 0; k < 64; k++) {
        float acc = (lane < 16) ? g_Bm[(t0 + k)*16 + lane] : 0.f;
        #pragma unroll
        for (int j = 0; j < 16; j++)
            acc = fmaf(mrow[j], __shfl_sync(0xffffffffu, h, j), acc);
        h = acc;
        if (lane < 16) g_H[(t0 + k)*16 + lane] = h;
    }
    if (lane < 16) sE[w*16 + lane] = h;
    __syncthreads();
    if (w == 0) {
        float m64row[16];
        #pragma unroll
        for (int j = 0; j < 16; j++) m64row[j] = (lane < 16) ? sM64[lane*16 + j] : 0.f;
        float sv2 = (lane < 16) ? sE[lane] : 0.f;
        if (lane < 16) sS[lane] = sv2;
        for (int c = 1; c < 32; c++) {
            float acc = (lane < 16) ? sE[c*16 + lane] : 0.f;
            #pragma unroll
            for (int j = 0; j < 16; j++)
                acc = fmaf(m64row[j], __shfl_sync(0xffffffffu, sv2, j), acc);
            sv2 = acc;
            if (lane < 16) sS[c*16 + lane] = sv2;
        }
    }
    __syncthreads();
    float v = (w > 0 && lane < 16) ? sS[(w-1)*16 + lane] : 0.f;
    for (int k = 0; k < 64; k++) {
        if (w > 0) {
            float acc = 0.f;
            #pragma unroll
            for (int j = 0; j < 16; j++)
                acc = fmaf(mrow[j], __shfl_sync(0xffffffffu, v, j), acc);
            v = acc;
        }
        float hh = 0.f, cc = 0.f;
        if (lane < 16) {
            hh = g_H[(t0 + k)*16 + lane] + v;
            cc = g_Cm[(t0 + k)*16 + lane];
        }
        float p = hh * cc;
        p += __shfl_xor_sync(0xffffffffu, p, 8);
        p += __shfl_xor_sync(0xffffffffu, p, 4);
        p += __shfl_xor_sync(0xffffffffu, p, 2);
        p += __shfl_xor_sync(0xffffffffu, p, 1);
        if (lane == 0) g_sv[t0 + k] = p;
    }
}

// ---------------- y = clip(x_in * (s + Dp), +-1000), split output ----------
__global__ void y_k(const float* __restrict__ Dp)
{
    int idx = blockIdx.x * blockDim.x + threadIdx.x;
    if (idx >= SEQ * DIN) return;
    int t = idx >> 11, c = idx & (DIN - 1);
    float vv = g_xin[idx] * (g_sv[t] + Dp[c]);
    vv = fminf(fmaxf(vv, -1000.f), 1000.f);
    split_h(vv, g_yh[idx], g_yl[idx]);
}

// ---------------------------------------------------------------------------
extern "C" void kernel_launch(void* const* d_in, const int* in_sizes, int n_in,
                              void* d_out, int out_size)
{
    const float* x     = (const float*)d_in[0];
    const float* Wq    = (const float*)d_in[1];
    const float* bq    = (const float*)d_in[2];
    const float* Wk    = (const float*)d_in[3];
    const float* bk    = (const float*)d_in[4];
    const float* Wv    = (const float*)d_in[5];
    const float* bv    = (const float*)d_in[6];
    const float* Wo    = (const float*)d_in[7];
    const float* bo    = (const float*)d_in[8];
    const float* fc1w  = (const float*)d_in[9];
    const float* fc1b  = (const float*)d_in[10];
    const float* fc2w  = (const float*)d_in[11];
    const float* fc2b  = (const float*)d_in[12];
    const float* inw   = (const float*)d_in[13];
    const float* inb   = (const float*)d_in[14];
    const float* convw = (const float*)d_in[15];
    const float* convb = (const float*)d_in[16];
    const float* xpw   = (const float*)d_in[17];
    const float* xpb   = (const float*)d_in[18];
    const float* Amat  = (const float*)d_in[19];
    const float* Dp    = (const float*)d_in[20];
    // d_in[21] = dt_p: provably dead (delta cancels in the scan transition)
    const float* outw  = (const float*)d_in[22];
    const float* outb  = (const float*)d_in[23];
    const float* g1    = (const float*)d_in[24];
    const float* be1   = (const float*)d_in[25];
    const float* g2    = (const float*)d_in[26];
    const float* be2   = (const float*)d_in[27];
    const float* g3    = (const float*)d_in[28];
    const float* be3   = (const float*)d_in[29];
    float* out = (float*)d_out;

    float *p_x1, *p_xin, *p_mt, *p_x2, *p_xpp, *p_pp, *p_qkvb;
    __half *p_lnh,*p_lnl,*p_qkvh,*p_qkvl,*p_aoh,*p_aol,*p_xch,*p_xcl,*p_yh,*p_yl,*p_ffh,*p_ffl;
    __half *p_wqkvh,*p_wqkvl,*p_woh,*p_wol;
    __half *p_inh,*p_inl,*p_xph,*p_xpl,*p_oth,*p_otl,*p_f1h,*p_f1l,*p_f2h,*p_f2l;
    cudaGetSymbolAddress((void**)&p_x1,   g_x1);
    cudaGetSymbolAddress((void**)&p_xin,  g_xin);
    cudaGetSymbolAddress((void**)&p_mt,   g_mt);
    cudaGetSymbolAddress((void**)&p_x2,   g_x2);
    cudaGetSymbolAddress((void**)&p_xpp,  g_xpp);
    cudaGetSymbolAddress((void**)&p_pp,   g_pp);
    cudaGetSymbolAddress((void**)&p_qkvb, g_qkvb);
    cudaGetSymbolAddress((void**)&p_lnh, g_lnh); cudaGetSymbolAddress((void**)&p_lnl, g_lnl);
    cudaGetSymbolAddress((void**)&p_qkvh, g_qkvh); cudaGetSymbolAddress((void**)&p_qkvl, g_qkvl);
    cudaGetSymbolAddress((void**)&p_aoh, g_aoh); cudaGetSymbolAddress((void**)&p_aol, g_aol);
    cudaGetSymbolAddress((void**)&p_xch, g_xch); cudaGetSymbolAddress((void**)&p_xcl, g_xcl);
    cudaGetSymbolAddress((void**)&p_yh,  g_yh);  cudaGetSymbolAddress((void**)&p_yl,  g_yl);
    cudaGetSymbolAddress((void**)&p_ffh, g_ffh); cudaGetSymbolAddress((void**)&p_ffl, g_ffl);
    cudaGetSymbolAddress((void**)&p_wqkvh, g_wqkvh); cudaGetSymbolAddress((void**)&p_wqkvl, g_wqkvl);
    cudaGetSymbolAddress((void**)&p_woh, g_woh); cudaGetSymbolAddress((void**)&p_wol, g_wol);
    cudaGetSymbolAddress((void**)&p_inh, g_inh); cudaGetSymbolAddress((void**)&p_inl, g_inl);
    cudaGetSymbolAddress((void**)&p_xph, g_xph); cudaGetSymbolAddress((void**)&p_xpl, g_xpl);
    cudaGetSymbolAddress((void**)&p_oth, g_oth); cudaGetSymbolAddress((void**)&p_otl, g_otl);
    cudaGetSymbolAddress((void**)&p_f1h, g_f1h); cudaGetSymbolAddress((void**)&p_f1l, g_f1l);
    cudaGetSymbolAddress((void**)&p_f2h, g_f2h); cudaGetSymbolAddress((void**)&p_f2l, g_f2l);

    cudaFuncSetAttribute(gemm2<0,false,false>, cudaFuncAttributeMaxDynamicSharedMemorySize, GEMM_SMEM);
    cudaFuncSetAttribute(gemm2<1,false,false>, cudaFuncAttributeMaxDynamicSharedMemorySize, GEMM_SMEM);
    cudaFuncSetAttribute(gemm2<1,true,false>,  cudaFuncAttributeMaxDynamicSharedMemorySize, GEMM_SMEM);
    cudaFuncSetAttribute(gemm2<2,false,false>, cudaFuncAttributeMaxDynamicSharedMemorySize, GEMM_SMEM);
    cudaFuncSetAttribute(attn_k, cudaFuncAttributeMaxDynamicSharedMemorySize, ATTN_SMEM);

    // --- weight pre-split (deterministic each call) ---
    wsplit_k<<<(DM*DM+255)/256, 256>>>(Wq,   p_wqkvh,           p_wqkvl,           DM,  DM,  DM);
    wsplit_k<<<(DM*DM+255)/256, 256>>>(Wk,   p_wqkvh + DM*DM,   p_wqkvl + DM*DM,   DM,  DM,  DM);
    wsplit_k<<<(DM*DM+255)/256, 256>>>(Wv,   p_wqkvh + 2*DM*DM, p_wqkvl + 2*DM*DM, DM,  DM,  DM);
    catb_k<<<(3*DM+255)/256, 256>>>(bq, bk, bv);
    wsplit_k<<<(DM*DM+255)/256, 256>>>(Wo,   p_woh, p_wol, DM,  DM,  DM);
    wsplit_k<<<(DIN*DM+255)/256, 256>>>(inw, p_inh, p_inl, DIN, DM,  DIN);
    wsplit_k<<<(128*DIN+255)/256, 256>>>(xpw,p_xph, p_xpl, XPN, DIN, 128);
    wsplit_k<<<(DM*DIN+255)/256, 256>>>(outw,p_oth, p_otl, DM,  DIN, DM);
    wsplit_k<<<(DFF*DM+255)/256, 256>>>(fc1w,p_f1h, p_f1l, DFF, DM,  DFF);
    wsplit_k<<<(DM*DFF+255)/256, 256>>>(fc2w,p_f2h, p_f2l, DM,  DFF, DM);

    // --- block 1: attention ---
    ln_k<true,false,false,true><<<SEQ, 256>>>(x, g1, be1, nullptr, nullptr, p_lnh, p_lnl);
    gemm2<1,false,false><<<dim3(24,16), 256, GEMM_SMEM>>>(p_lnh,p_lnl, p_wqkvh,p_wqkvl, p_qkvb, nullptr, nullptr, p_qkvh,p_qkvl, SEQ, 3*DM, DM);
    attn_k<<<dim3(SEQ/64, NH), 128, ATTN_SMEM>>>(p_qkvh, p_qkvl, p_aoh, p_aol);
    gemm2<2,false,false><<<dim3(8,16,2), 256, GEMM_SMEM>>>(p_aoh,p_aol, p_woh,p_wol, nullptr, nullptr, p_pp, nullptr,nullptr, SEQ, DM, DM);
    reduce2_k<true><<<(SEQ*DM+255)/256, 256>>>(p_pp, bo, x, p_x1);

    // --- block 2: mamba ---
    ln2_k<<<SEQ, 256>>>(p_x1, g2, be2, p_lnh, p_lnl);
    gemm2<0,false,false><<<dim3(16,16), 256, GEMM_SMEM>>>(p_lnh,p_lnl, p_inh,p_inl, inb, nullptr, p_xin, nullptr,nullptr, SEQ, DIN, DM);
    conv_k<<<SEQ*DIN/256, 256>>>(convw, convb);
    gemm2<2,false,false><<<dim3(1,16,KSPL), 256, GEMM_SMEM>>>(p_xch,p_xcl, p_xph,p_xpl, nullptr, nullptr, p_xpp, nullptr,nullptr, SEQ, 128, DIN);
    reduce_xp<<<(SEQ*XPN+255)/256, 256>>>(xpb);
    bc_k<<<SEQ, 32>>>();
    buildM_k<<<1, 256>>>(Amat);
    scan_k<<<1, 1024>>>();
    y_k<<<SEQ*DIN/256, 256>>>(Dp);
    gemm2<2,false,false><<<dim3(8,16,2), 256, GEMM_SMEM>>>(p_yh,p_yl, p_oth,p_otl, nullptr, nullptr, p_pp, nullptr,nullptr, SEQ, DM, DIN);
    reduce2_k<false><<<(SEQ*DM+255)/256, 256>>>(p_pp, outb, nullptr, p_mt);
    ln_k<false,true,true,false><<<SEQ, 256>>>(p_mt, nullptr, nullptr, p_x1, p_x2, nullptr, nullptr);

    // --- block 3: FFN ---
    ln_k<true,false,false,true><<<SEQ, 256>>>(p_x2, g3, be3, nullptr, nullptr, p_lnh, p_lnl);
    gemm2<1,true,false><<<dim3(32,16), 256, GEMM_SMEM>>>(p_lnh,p_lnl, p_f1h,p_f1l, fc1b, nullptr, nullptr, p_ffh,p_ffl, SEQ, DFF, DM);
    gemm2<2,false,false><<<dim3(8,16,2), 256, GEMM_SMEM>>>(p_ffh,p_ffl, p_f2h,p_f2l, nullptr, nullptr, p_pp, nullptr,nullptr, SEQ, DM, DFF);
    reduce2_k<true><<<(SEQ*DM+255)/256, 256>>>(p_pp, fc2b, p_x2, out);
}

// round 17
// speedup vs baseline: 1.0965x; 1.0965x over previous
#include <cuda_runtime.h>
#include <cuda_fp16.h>
#include <stdint.h>
#include <math.h>

#define SEQ 2048
#define DM  1024
#define DFF 4096
#define DIN 2048
#define NH  16
#define XPN 96
#define DST 16
#define KSPL 8

// ---------------- fp32 scratch ---------------------------------------------
__device__ float g_ln  [SEQ*DM];
__device__ float g_x1  [SEQ*DM];
__device__ float g_xin [SEQ*DIN];
__device__ float g_xdbc[SEQ*XPN];
__device__ float g_Bm  [SEQ*DST];
__device__ float g_Cm  [SEQ*DST];
__device__ float g_H   [SEQ*DST];
__device__ float g_sv  [SEQ];
__device__ float g_mt  [SEQ*DM];
__device__ float g_x2  [SEQ*DM];
__device__ float g_M   [256];
__device__ float g_M64 [256];
__device__ float g_xpp [KSPL*SEQ*128];  // split-K partials for xp gemm
__device__ float g_pp  [2*SEQ*DM];      // split-K2 partials (N=1024 gemms)
__device__ float g_qkvb[3*DM];          // concatenated q|k|v bias

// ---------------- fp16 hi/lo split scratch (activations) -------------------
__device__ __align__(256) __half g_lnh[SEQ*DM],  g_lnl[SEQ*DM];
__device__ __align__(256) __half g_qkvh[SEQ*3*DM], g_qkvl[SEQ*3*DM];
__device__ __align__(256) __half g_aoh[SEQ*DM],  g_aol[SEQ*DM];
__device__ __align__(256) __half g_xch[SEQ*DIN], g_xcl[SEQ*DIN];
__device__ __align__(256) __half g_yh [SEQ*DIN], g_yl [SEQ*DIN];
__device__ __align__(256) __half g_ffh[SEQ*DFF], g_ffl[SEQ*DFF];
// ---------------- fp16 hi/lo split scratch (weights) -----------------------
__device__ __align__(256) __half g_wqkvh[3*DM*DM], g_wqkvl[3*DM*DM];
__device__ __align__(256) __half g_woh[DM*DM],   g_wol[DM*DM];
__device__ __align__(256) __half g_inh[DIN*DM],  g_inl[DIN*DM];
__device__ __align__(256) __half g_xph[128*DIN], g_xpl[128*DIN];
__device__ __align__(256) __half g_oth[DM*DIN],  g_otl[DM*DIN];
__device__ __align__(256) __half g_f1h[DFF*DM],  g_f1l[DFF*DM];
__device__ __align__(256) __half g_f2h[DM*DFF],  g_f2l[DM*DFF];

// ---------------- helpers ---------------------------------------------------
__device__ __forceinline__ void split_h(float v, __half& h, __half& l) {
    h = __float2half_rn(v);
    l = __float2half_rn(v - __half2float(h));
}
__device__ __forceinline__ void sp2(float a, float b, uint32_t& hi, uint32_t& lo) {
    __half ha = __float2half_rn(a), hb = __float2half_rn(b);
    __half la = __float2half_rn(a - __half2float(ha));
    __half lb = __float2half_rn(b - __half2float(hb));
    hi = ((uint32_t)__half_as_ushort(hb) << 16) | __half_as_ushort(ha);
    lo = ((uint32_t)__half_as_ushort(lb) << 16) | __half_as_ushort(la);
}
__device__ __forceinline__ void mma_f16(float* d, const uint32_t* a,
                                        const uint32_t* b, const float* c) {
    asm volatile(
        "mma.sync.aligned.m16n8k16.row.col.f32.f16.f16.f32 "
        "{%0,%1,%2,%3}, {%4,%5,%6,%7}, {%8,%9}, {%10,%11,%12,%13};\n"
        : "=f"(d[0]), "=f"(d[1]), "=f"(d[2]), "=f"(d[3])
        : "r"(a[0]), "r"(a[1]), "r"(a[2]), "r"(a[3]),
          "r"(b[0]), "r"(b[1]),
          "f"(c[0]), "f"(c[1]), "f"(c[2]), "f"(c[3]));
}
__device__ __forceinline__ void ldsm4(uint32_t addr, uint32_t* r) {
    asm volatile("ldmatrix.sync.aligned.m8n8.x4.shared.b16 {%0,%1,%2,%3}, [%4];"
                 : "=r"(r[0]), "=r"(r[1]), "=r"(r[2]), "=r"(r[3]) : "r"(addr));
}
__device__ __forceinline__ void ldsm4t(uint32_t addr, uint32_t* r) {
    asm volatile("ldmatrix.sync.aligned.m8n8.x4.trans.shared.b16 {%0,%1,%2,%3}, [%4];"
                 : "=r"(r[0]), "=r"(r[1]), "=r"(r[2]), "=r"(r[3]) : "r"(addr));
}
__device__ __forceinline__ void ldsm2(uint32_t addr, uint32_t* r) {
    asm volatile("ldmatrix.sync.aligned.m8n8.x2.shared.b16 {%0,%1}, [%2];"
                 : "=r"(r[0]), "=r"(r[1]) : "r"(addr));
}
__device__ __forceinline__ void cp16(uint32_t s, const void* g) {
    asm volatile("cp.async.cg.shared.global [%0], [%1], 16;\n"
                 :: "r"(s), "l"(g) : "memory");
}

// ---------------- weight split: W (N,K) -> hi/lo (Npad,K), zero padding ----
__global__ void wsplit_k(const float* __restrict__ W,
                         __half* __restrict__ h, __half* __restrict__ l,
                         int N, int K, int Npad)
{
    int idx = blockIdx.x * blockDim.x + threadIdx.x;
    if (idx >= Npad * K) return;
    int row = idx / K;
    float v = (row < N) ? W[idx] : 0.f;
    split_h(v, h[idx], l[idx]);
}

// ---------------- concat q|k|v biases --------------------------------------
__global__ void catb_k(const float* __restrict__ bq, const float* __restrict__ bk,
                       const float* __restrict__ bv)
{
    int i = blockIdx.x * blockDim.x + threadIdx.x;
    if (i >= 3*DM) return;
    g_qkvb[i] = (i < DM) ? bq[i] : (i < 2*DM) ? bk[i - DM] : bv[i - 2*DM];
}

// ------- split-fp16 GEMM: 3 products hh+hl+lh, ldmatrix + m16n8k16 ---------
// A,B as fp16 hi/lo arrays. A: (M,K), B: (Npad,K) row-major.
// OM: 0 = fp32 out (+bias)(+res), 1 = (GELU+) split out (+bias), 2 = split-K.
// Tile 128x128, BK=32, 256 thr = 2x4 warps; warp 64x32 via 4x4 m16n8k16.
#define AWH 5120        // halves per array (128*40)
template<int OM, bool GELU, bool RES>
__global__ void __launch_bounds__(256) gemm2(
    const __half* __restrict__ Ah, const __half* __restrict__ Al,
    const __half* __restrict__ Bh, const __half* __restrict__ Bl,
    const float* __restrict__ bias, const float* __restrict__ res,
    float* __restrict__ C, __half* __restrict__ Ch, __half* __restrict__ Cl,
    int M, int N, int K)
{
    extern __shared__ __half smh[];   // [2 buf][Ah,Al,Bh,Bl][AWH]
    const int tid = threadIdx.x;
    const int warp = tid >> 5, lane = tid & 31;
    const int g = lane >> 2, tig = lane & 3;
    const int wm = warp >> 2, wn = warp & 3;
    const int bm = blockIdx.y * 128, bn = blockIdx.x * 128;

    int kb = 0, klen = K;
    if (OM == 2) { klen = K / gridDim.z; kb = blockIdx.z * klen; }
    const int nk = klen >> 5;

    const uint32_t sbase = (uint32_t)__cvta_generic_to_shared(smh);

    const int rsel = (lane & 7) + ((lane >> 3) & 1) * 8;
    const int csel = ((lane >> 4) & 1) * 8;
    const int l16  = lane & 15;
    const int brsel = l16 & 7;
    const int bcsel = ((l16 >> 3) & 1) * 8;

    float acc[4][4][4];
    #pragma unroll
    for (int i = 0; i < 4; i++)
        #pragma unroll
        for (int j = 0; j < 4; j++)
            #pragma unroll
            for (int r = 0; r < 4; r++) acc[i][j][r] = 0.f;

    auto issue = [&](int kt, int buf) {
        const int k0 = kb + (kt << 5);
        #pragma unroll
        for (int u = 0; u < 2; u++) {
            const int id = tid + (u << 8);
            const int row = id >> 2, ch = (id & 3) << 3;
            const uint32_t so = sbase + (row * 40 + ch) * 2;
            const size_t ga = (size_t)(bm + row) * K + k0 + ch;
            const size_t gb = (size_t)(bn + row) * K + k0 + ch;
            cp16(so + (buf*4 + 0) * (AWH*2), Ah + ga);
            cp16(so + (buf*4 + 1) * (AWH*2), Al + ga);
            cp16(so + (buf*4 + 2) * (AWH*2), Bh + gb);
            cp16(so + (buf*4 + 3) * (AWH*2), Bl + gb);
        }
        asm volatile("cp.async.commit_group;\n" ::: "memory");
    };

    issue(0, 0);

    for (int kt = 0; kt < nk; kt++) {
        const int buf = kt & 1;
        if (kt + 1 < nk) {
            issue(kt + 1, buf ^ 1);
            asm volatile("cp.async.wait_group 1;\n" ::: "memory");
        } else {
            asm volatile("cp.async.wait_group 0;\n" ::: "memory");
        }
        __syncthreads();
        const uint32_t bAh = sbase + (buf*4 + 0) * (AWH*2);
        const uint32_t bAl = sbase + (buf*4 + 1) * (AWH*2);
        const uint32_t bBh = sbase + (buf*4 + 2) * (AWH*2);
        const uint32_t bBl = sbase + (buf*4 + 3) * (AWH*2);
        #pragma unroll
        for (int ks = 0; ks < 2; ks++) {
            uint32_t ah[4][4], al[4][4], bh[4][2], bl[4][2];
            #pragma unroll
            for (int i = 0; i < 4; i++) {
                const uint32_t ao = ((wm*64 + i*16 + rsel) * 40 + ks*16 + csel) * 2;
                ldsm4(bAh + ao, ah[i]);
                ldsm4(bAl + ao, al[i]);
            }
            #pragma unroll
            for (int j = 0; j < 4; j++) {
                const uint32_t bo = ((wn*32 + j*8 + brsel) * 40 + ks*16 + bcsel) * 2;
                ldsm2(bBh + bo, bh[j]);
                ldsm2(bBl + bo, bl[j]);
            }
            #pragma unroll
            for (int i = 0; i < 4; i++)
                #pragma unroll
                for (int j = 0; j < 4; j++) {
                    mma_f16(acc[i][j], ah[i], bh[j], acc[i][j]);
                    mma_f16(acc[i][j], ah[i], bl[j], acc[i][j]);
                    mma_f16(acc[i][j], al[i], bh[j], acc[i][j]);
                }
        }
        __syncthreads();
    }

    // epilogue (m16n8 output frag: c0,c1 = row g; c2,c3 = row g+8)
    #pragma unroll
    for (int i = 0; i < 4; i++) {
        const int r0 = bm + wm*64 + i*16 + g;
        const int r1 = r0 + 8;
        #pragma unroll
        for (int j = 0; j < 4; j++) {
            const int c = bn + wn*32 + j*8 + 2*tig;
            float v0 = acc[i][j][0], v1 = acc[i][j][1];
            float v2 = acc[i][j][2], v3 = acc[i][j][3];
            if (OM == 2) {
                float* Cp = C + (size_t)blockIdx.z * M * N;
                *(float2*)&Cp[(size_t)r0*N + c] = make_float2(v0, v1);
                *(float2*)&Cp[(size_t)r1*N + c] = make_float2(v2, v3);
            } else if (c < N) {
                if (bias) {
                    const float b0 = bias[c], b1 = bias[c+1];
                    v0 += b0; v1 += b1; v2 += b0; v3 += b1;
                }
                if (RES) {
                    v0 += res[(size_t)r0*N + c];
                    v1 += res[(size_t)r0*N + c + 1];
                    v2 += res[(size_t)r1*N + c];
                    v3 += res[(size_t)r1*N + c + 1];
                }
                if (GELU) {
                    #define GLU(u) (0.5f*(u)*(1.f + tanhf(0.7978845608f*((u) + 0.044715f*(u)*(u)*(u)))))
                    v0 = GLU(v0); v1 = GLU(v1); v2 = GLU(v2); v3 = GLU(v3);
                    #undef GLU
                }
                if (OM == 0) {
                    *(float2*)&C[(size_t)r0*N + c] = make_float2(v0, v1);
                    *(float2*)&C[(size_t)r1*N + c] = make_float2(v2, v3);
                } else {   // OM==1: split output
                    split_h(v0, Ch[(size_t)r0*N + c],     Cl[(size_t)r0*N + c]);
                    split_h(v1, Ch[(size_t)r0*N + c + 1], Cl[(size_t)r0*N + c + 1]);
                    split_h(v2, Ch[(size_t)r1*N + c],     Cl[(size_t)r1*N + c]);
                    split_h(v3, Ch[(size_t)r1*N + c + 1], Cl[(size_t)r1*N + c + 1]);
                }
            }
        }
    }
}
#define GEMM_SMEM (2 * 4 * AWH * 2)   // 81920 bytes

// ---------------- reduce split-K2 partials (N=1024 gemms) ------------------
template<bool RES>
__global__ void reduce2_k(const float* __restrict__ P, const float* __restrict__ bias,
                          const float* __restrict__ res, float* __restrict__ C)
{
    int idx = blockIdx.x * blockDim.x + threadIdx.x;
    if (idx >= SEQ * DM) return;
    float v = P[idx] + P[idx + SEQ*DM] + bias[idx & (DM-1)];
    if (RES) v += res[idx];
    C[idx] = v;
}

// ---------------- reduce split-K partials for xp gemm ----------------------
__global__ void reduce_xp(const float* __restrict__ xpb)
{
    int idx = blockIdx.x * blockDim.x + threadIdx.x;
    if (idx >= SEQ * XPN) return;
    int m = idx / XPN, n = idx - m * XPN;
    float s = xpb[n];
    #pragma unroll
    for (int z = 0; z < KSPL; z++)
        s += g_xpp[((size_t)z * SEQ + m) * 128 + n];
    g_xdbc[idx] = s;
}

// ---------------- MMA flash attention (split fp16, fp32 softmax) -----------
// QKV split fp16, row stride 3072 (q|k|v). grid (SEQ/64, NH), 128 threads.
// Warp w: 16 q-rows. S = Q K^T and O += P V via m16n8k16 with 3-product split.
#define ALD 72
#define ATTN_SMEM (6 * 64 * ALD * 2)
__global__ void __launch_bounds__(128) attn_k(
    const __half* __restrict__ QKVh, const __half* __restrict__ QKVl,
    __half* __restrict__ Oh, __half* __restrict__ Ol)
{
    extern __shared__ __half sa[];
    const uint32_t sb = (uint32_t)__cvta_generic_to_shared(sa);
    const uint32_t bQh = sb;
    const uint32_t bQl = bQh + 64*ALD*2;
    const uint32_t bKh = bQl + 64*ALD*2;
    const uint32_t bKl = bKh + 64*ALD*2;
    const uint32_t bVh = bKl + 64*ALD*2;
    const uint32_t bVl = bVh + 64*ALD*2;

    const int tid = threadIdx.x;
    const int warp = tid >> 5, lane = tid & 31;
    const int g = lane >> 2, tig = lane & 3;
    const int q0 = blockIdx.x * 64;
    const int cb = blockIdx.y * 64;
    const int LDM = 3*DM;

    const int rsel = (lane & 7) + ((lane >> 3) & 1) * 8;
    const int csel = ((lane >> 4) & 1) * 8;

    // load Q tile (hi/lo)
    #pragma unroll
    for (int u = 0; u < 4; u++) {
        const int id = tid + u*128;
        const int r = id >> 3, ch = (id & 7) * 8;
        const uint32_t so = (r * ALD + ch) * 2;
        const size_t go = (size_t)(q0 + r) * LDM + cb + ch;
        cp16(bQh + so, QKVh + go);
        cp16(bQl + so, QKVl + go);
    }
    asm volatile("cp.async.commit_group;\n" ::: "memory");

    float m_i[2] = {-1e30f, -1e30f};
    float l_i[2] = {0.f, 0.f};
    float oacc[8][4];
    #pragma unroll
    for (int j = 0; j < 8; j++)
        #pragma unroll
        for (int r = 0; r < 4; r++) oacc[j][r] = 0.f;

    for (int kt = 0; kt < SEQ/64; kt++) {
        // load K,V tiles (hi/lo)
        #pragma unroll
        for (int u = 0; u < 4; u++) {
            const int id = tid + u*128;
            const int r = id >> 3, ch = (id & 7) * 8;
            const uint32_t so = (r * ALD + ch) * 2;
            const size_t gk = (size_t)(kt*64 + r) * LDM + DM + cb + ch;
            cp16(bKh + so, QKVh + gk);
            cp16(bKl + so, QKVl + gk);
            cp16(bVh + so, QKVh + gk + DM);
            cp16(bVl + so, QKVl + gk + DM);
        }
        asm volatile("cp.async.commit_group;\n" ::: "memory");
        asm volatile("cp.async.wait_group 0;\n" ::: "memory");
        __syncthreads();

        // S = Q K^T (warp M=16, N=64, K=64)
        float s[8][4];
        #pragma unroll
        for (int j = 0; j < 8; j++)
            #pragma unroll
            for (int r = 0; r < 4; r++) s[j][r] = 0.f;
        #pragma unroll
        for (int ks = 0; ks < 4; ks++) {
            uint32_t qh[4], ql[4];
            const uint32_t ao = ((warp*16 + rsel) * ALD + ks*16 + csel) * 2;
            ldsm4(bQh + ao, qh);
            ldsm4(bQl + ao, ql);
            #pragma unroll
            for (int jj = 0; jj < 4; jj++) {
                uint32_t t0[4], t1[4];
                const uint32_t bo = ((jj*16 + rsel) * ALD + ks*16 + csel) * 2;
                ldsm4(bKh + bo, t0);
                ldsm4(bKl + bo, t1);
                uint32_t bhA[2] = {t0[0], t0[2]}, bhB[2] = {t0[1], t0[3]};
                uint32_t blA[2] = {t1[0], t1[2]}, blB[2] = {t1[1], t1[3]};
                mma_f16(s[2*jj],   qh, bhA, s[2*jj]);
                mma_f16(s[2*jj],   qh, blA, s[2*jj]);
                mma_f16(s[2*jj],   ql, bhA, s[2*jj]);
                mma_f16(s[2*jj+1], qh, bhB, s[2*jj+1]);
                mma_f16(s[2*jj+1], qh, blB, s[2*jj+1]);
                mma_f16(s[2*jj+1], ql, bhB, s[2*jj+1]);
            }
        }
        // online softmax (rows g and g+8 of warp tile)
        float mx0 = -1e30f, mx1 = -1e30f;
        #pragma unroll
        for (int j = 0; j < 8; j++) {
            s[j][0] *= 0.125f; s[j][1] *= 0.125f;
            s[j][2] *= 0.125f; s[j][3] *= 0.125f;
            mx0 = fmaxf(mx0, fmaxf(s[j][0], s[j][1]));
            mx1 = fmaxf(mx1, fmaxf(s[j][2], s[j][3]));
        }
        mx0 = fmaxf(mx0, __shfl_xor_sync(0xffffffffu, mx0, 1));
        mx0 = fmaxf(mx0, __shfl_xor_sync(0xffffffffu, mx0, 2));
        mx1 = fmaxf(mx1, __shfl_xor_sync(0xffffffffu, mx1, 1));
        mx1 = fmaxf(mx1, __shfl_xor_sync(0xffffffffu, mx1, 2));
        const float mn0 = fmaxf(m_i[0], mx0), mn1 = fmaxf(m_i[1], mx1);
        const float sc0 = __expf(m_i[0] - mn0), sc1 = __expf(m_i[1] - mn1);
        float sum0 = 0.f, sum1 = 0.f;
        #pragma unroll
        for (int j = 0; j < 8; j++) {
            s[j][0] = __expf(s[j][0] - mn0); sum0 += s[j][0];
            s[j][1] = __expf(s[j][1] - mn0); sum0 += s[j][1];
            s[j][2] = __expf(s[j][2] - mn1); sum1 += s[j][2];
            s[j][3] = __expf(s[j][3] - mn1); sum1 += s[j][3];
        }
        sum0 += __shfl_xor_sync(0xffffffffu, sum0, 1);
        sum0 += __shfl_xor_sync(0xffffffffu, sum0, 2);
        sum1 += __shfl_xor_sync(0xffffffffu, sum1, 1);
        sum1 += __shfl_xor_sync(0xffffffffu, sum1, 2);
        l_i[0] = l_i[0]*sc0 + sum0;
        l_i[1] = l_i[1]*sc1 + sum1;
        m_i[0] = mn0; m_i[1] = mn1;
        #pragma unroll
        for (int j = 0; j < 8; j++) {
            oacc[j][0] *= sc0; oacc[j][1] *= sc0;
            oacc[j][2] *= sc1; oacc[j][3] *= sc1;
        }
        // O += P V  (P repacked in-register, V via trans ldmatrix)
        #pragma unroll
        for (int ks2 = 0; ks2 < 4; ks2++) {
            uint32_t ph[4], pl[4];
            sp2(s[2*ks2][0],   s[2*ks2][1],   ph[0], pl[0]);
            sp2(s[2*ks2][2],   s[2*ks2][3],   ph[1], pl[1]);
            sp2(s[2*ks2+1][0], s[2*ks2+1][1], ph[2], pl[2]);
            sp2(s[2*ks2+1][2], s[2*ks2+1][3], ph[3], pl[3]);
            #pragma unroll
            for (int jj = 0; jj < 4; jj++) {
                uint32_t t0[4], t1[4];
                const uint32_t vo = ((ks2*16 + rsel) * ALD + jj*16 + csel) * 2;
                ldsm4t(bVh + vo, t0);
                ldsm4t(bVl + vo, t1);
                uint32_t vA[2] = {t0[0], t0[1]}, vB[2] = {t0[2], t0[3]};
                uint32_t wA[2] = {t1[0], t1[1]}, wB[2] = {t1[2], t1[3]};
                mma_f16(oacc[2*jj],   ph, vA, oacc[2*jj]);
                mma_f16(oacc[2*jj],   ph, wA, oacc[2*jj]);
                mma_f16(oacc[2*jj],   pl, vA, oacc[2*jj]);
                mma_f16(oacc[2*jj+1], ph, vB, oacc[2*jj+1]);
                mma_f16(oacc[2*jj+1], ph, wB, oacc[2*jj+1]);
                mma_f16(oacc[2*jj+1], pl, vB, oacc[2*jj+1]);
            }
        }
        __syncthreads();
    }
    // finalize + split output
    const float li0 = 1.f / l_i[0], li1 = 1.f / l_i[1];
    const int row0 = q0 + warp*16 + g, row1 = row0 + 8;
    #pragma unroll
    for (int j = 0; j < 8; j++) {
        const int col = cb + j*8 + 2*tig;
        split_h(oacc[j][0]*li0, Oh[(size_t)row0*DM + col],   Ol[(size_t)row0*DM + col]);
        split_h(oacc[j][1]*li0, Oh[(size_t)row0*DM + col+1], Ol[(size_t)row0*DM + col+1]);
        split_h(oacc[j][2]*li1, Oh[(size_t)row1*DM + col],   Ol[(size_t)row1*DM + col]);
        split_h(oacc[j][3]*li1, Oh[(size_t)row1*DM + col+1], Ol[(size_t)row1*DM + col+1]);
    }
}

// ---------------- LayerNorm ------------------------------------------------
template<bool AFF, bool RES, bool WF, bool WS>
__global__ void __launch_bounds__(256) ln_k(
    const float* __restrict__ X, const float* __restrict__ g,
    const float* __restrict__ b, const float* __restrict__ res,
    float* __restrict__ Y, __half* __restrict__ Yh, __half* __restrict__ Yl)
{
    const int row = blockIdx.x;
    const float* x = X + (size_t)row * DM;
    const int tid = threadIdx.x;
    float v[4];
    float s = 0.f;
    #pragma unroll
    for (int u = 0; u < 4; u++) { v[u] = x[tid + 256*u]; s += v[u]; }
    __shared__ float red[8];
    __shared__ float stat[2];
    #pragma unroll
    for (int off = 16; off; off >>= 1) s += __shfl_xor_sync(0xffffffffu, s, off);
    if ((tid & 31) == 0) red[tid >> 5] = s;
    __syncthreads();
    if (tid == 0) {
        float t = 0.f;
        for (int k2 = 0; k2 < 8; k2++) t += red[k2];
        stat[0] = t * (1.f/1024.f);
    }
    __syncthreads();
    float mu = stat[0];
    float q = 0.f;
    #pragma unroll
    for (int u = 0; u < 4; u++) { float d = v[u] - mu; q += d*d; }
    #pragma unroll
    for (int off = 16; off; off >>= 1) q += __shfl_xor_sync(0xffffffffu, q, off);
    if ((tid & 31) == 0) red[tid >> 5] = q;
    __syncthreads();
    if (tid == 0) {
        float t = 0.f;
        for (int k2 = 0; k2 < 8; k2++) t += red[k2];
        stat[1] = rsqrtf(t * (1.f/1024.f) + 1e-5f);
    }
    __syncthreads();
    float rstd = stat[1];
    #pragma unroll
    for (int u = 0; u < 4; u++) {
        int c = tid + 256*u;
        float o = (v[u] - mu) * rstd;
        if (AFF) o = o * g[c] + b[c];
        if (RES) o += res[(size_t)row * DM + c];
        const size_t idx = (size_t)row * DM + c;
        if (WF) Y[idx] = o;
        if (WS) split_h(o, Yh[idx], Yl[idx]);
    }
}

// ---------------- depthwise causal conv1d (k=4), split output --------------
__global__ void conv_k(const float* __restrict__ cw, const float* __restrict__ cb)
{
    int idx = blockIdx.x * blockDim.x + threadIdx.x;
    if (idx >= SEQ * DIN) return;
    int t = idx >> 11, c = idx & (DIN - 1);
    float acc = cb[c];
    #pragma unroll
    for (int k = 0; k < 4; k++) {
        int ts = t + k - 3;
        if (ts >= 0) acc = fmaf(cw[c*4 + k], g_xin[(size_t)ts * DIN + c], acc);
    }
    split_h(acc, g_xch[idx], g_xcl[idx]);
}

// ---------------- B/C extraction: LN96 then LN16 ---------------------------
__global__ void bc_k()
{
    const int row = blockIdx.x;
    const int lane = threadIdx.x;
    const float* xr = g_xdbc + (size_t)row * XPN;
    float a0 = xr[lane], a1 = xr[lane + 32], a2 = xr[lane + 64];
    float s = a0 + a1 + a2;
    #pragma unroll
    for (int off = 16; off; off >>= 1) s += __shfl_xor_sync(0xffffffffu, s, off);
    float mu = s * (1.f/96.f);
    float d0 = a0-mu, d1 = a1-mu, d2 = a2-mu;
    float q = d0*d0 + d1*d1 + d2*d2;
    #pragma unroll
    for (int off = 16; off; off >>= 1) q += __shfl_xor_sync(0xffffffffu, q, off);
    float rstd = rsqrtf(q * (1.f/96.f) + 1e-5f);
    float vv = d2 * rstd;
    float hs = vv;
    #pragma unroll
    for (int off = 8; off; off >>= 1) hs += __shfl_xor_sync(0xffffffffu, hs, off);
    float m16 = hs * (1.f/16.f);
    float dd = vv - m16;
    float qq = dd * dd;
    #pragma unroll
    for (int off = 8; off; off >>= 1) qq += __shfl_xor_sync(0xffffffffu, qq, off);
    float o = dd * rsqrtf(qq * (1.f/16.f) + 1e-5f);
    if (lane < 16) g_Bm[row*16 + lane] = o;
    else           g_Cm[row*16 + lane - 16] = o;
}

// ---------------- build M and M^64 -----------------------------------------
__global__ void __launch_bounds__(256) buildM_k(const float* __restrict__ A)
{
    __shared__ float sred[256], sP[256];
    const int t = threadIdx.x;
    const int i = t >> 4, j = t & 15;
    float la = logf(fabsf(A[j*16 + i]) + 1e-8f);
    sred[t] = la;
    __syncthreads();
    for (int off = 128; off > 0; off >>= 1) {
        if (t < off) sred[t] = fminf(sred[t], sred[t + off]);
        __syncthreads();
    }
    float mn = sred[0];
    float Mv = expf(mn - la);
    Mv = fminf(fmaxf(Mv, 1e-4f), 1e4f);
    g_M[t] = Mv;
    sP[t] = Mv;
    __syncthreads();
    for (int it = 0; it < 6; ++it) {
        float acc = 0.f;
        #pragma unroll
        for (int k = 0; k < 16; k++) acc = fmaf(sP[i*16 + k], sP[k*16 + j], acc);
        __syncthreads();
        sP[t] = acc;
        __syncthreads();
    }
    g_M64[t] = sP[t];
}

// ---------------- chunked parallel scan ------------------------------------
__global__ void __launch_bounds__(1024) scan_k()
{
    __shared__ float sM[256], sM64[256], sE[32*16], sS[32*16];
    const int tid = threadIdx.x;
    if (tid < 256) { sM[tid] = g_M[tid]; sM64[tid] = g_M64[tid]; }
    __syncthreads();
    const int w = tid >> 5, lane = tid & 31;
    float mrow[16];
    #pragma unroll
    for (int j = 0; j < 16; j++) mrow[j] = (lane < 16) ? sM[lane*16 + j] : 0.f;
    const int t0 = w * 64;
    float h = 0.f;
    for (int k = 0; k < 64; k++) {
        float acc = (lane < 16) ? g_Bm[(t0 + k)*16 + lane] : 0.f;
        #pragma unroll
        for (int j = 0; j < 16; j++)
            acc = fmaf(mrow[j], __shfl_sync(0xffffffffu, h, j), acc);
        h = acc;
        if (lane < 16) g_H[(t0 + k)*16 + lane] = h;
    }
    if (lane < 16) sE[w*16 + lane] = h;
    __syncthreads();
    if (w == 0) {
        float m64row[16];
        #pragma unroll
        for (int j = 0; j < 16; j++) m64row[j] = (lane < 16) ? sM64[lane*16 + j] : 0.f;
        float sv2 = (lane < 16) ? sE[lane] : 0.f;
        if (lane < 16) sS[lane] = sv2;
        for (int c = 1; c < 32; c++) {
            float acc = (lane < 16) ? sE[c*16 + lane] : 0.f;
            #pragma unroll
            for (int j = 0; j < 16; j++)
                acc = fmaf(m64row[j], __shfl_sync(0xffffffffu, sv2, j), acc);
            sv2 = acc;
            if (lane < 16) sS[c*16 + lane] = sv2;
        }
    }
    __syncthreads();
    float v = (w > 0 && lane < 16) ? sS[(w-1)*16 + lane] : 0.f;
    for (int k = 0; k < 64; k++) {
        if (w > 0) {
            float acc = 0.f;
            #pragma unroll
            for (int j = 0; j < 16; j++)
                acc = fmaf(mrow[j], __shfl_sync(0xffffffffu, v, j), acc);
            v = acc;
        }
        float hh = 0.f, cc = 0.f;
        if (lane < 16) {
            hh = g_H[(t0 + k)*16 + lane] + v;
            cc = g_Cm[(t0 + k)*16 + lane];
        }
        float p = hh * cc;
        p += __shfl_xor_sync(0xffffffffu, p, 8);
        p += __shfl_xor_sync(0xffffffffu, p, 4);
        p += __shfl_xor_sync(0xffffffffu, p, 2);
        p += __shfl_xor_sync(0xffffffffu, p, 1);
        if (lane == 0) g_sv[t0 + k] = p;
    }
}

// ---------------- y = clip(x_in * (s + Dp), +-1000), split output ----------
__global__ void y_k(const float* __restrict__ Dp)
{
    int idx = blockIdx.x * blockDim.x + threadIdx.x;
    if (idx >= SEQ * DIN) return;
    int t = idx >> 11, c = idx & (DIN - 1);
    float vv = g_xin[idx] * (g_sv[t] + Dp[c]);
    vv = fminf(fmaxf(vv, -1000.f), 1000.f);
    split_h(vv, g_yh[idx], g_yl[idx]);
}

// ---------------------------------------------------------------------------
extern "C" void kernel_launch(void* const* d_in, const int* in_sizes, int n_in,
                              void* d_out, int out_size)
{
    const float* x     = (const float*)d_in[0];
    const float* Wq    = (const float*)d_in[1];
    const float* bq    = (const float*)d_in[2];
    const float* Wk    = (const float*)d_in[3];
    const float* bk    = (const float*)d_in[4];
    const float* Wv    = (const float*)d_in[5];
    const float* bv    = (const float*)d_in[6];
    const float* Wo    = (const float*)d_in[7];
    const float* bo    = (const float*)d_in[8];
    const float* fc1w  = (const float*)d_in[9];
    const float* fc1b  = (const float*)d_in[10];
    const float* fc2w  = (const float*)d_in[11];
    const float* fc2b  = (const float*)d_in[12];
    const float* inw   = (const float*)d_in[13];
    const float* inb   = (const float*)d_in[14];
    const float* convw = (const float*)d_in[15];
    const float* convb = (const float*)d_in[16];
    const float* xpw   = (const float*)d_in[17];
    const float* xpb   = (const float*)d_in[18];
    const float* Amat  = (const float*)d_in[19];
    const float* Dp    = (const float*)d_in[20];
    // d_in[21] = dt_p: provably dead (delta cancels in the scan transition)
    const float* outw  = (const float*)d_in[22];
    const float* outb  = (const float*)d_in[23];
    const float* g1    = (const float*)d_in[24];
    const float* be1   = (const float*)d_in[25];
    const float* g2    = (const float*)d_in[26];
    const float* be2   = (const float*)d_in[27];
    const float* g3    = (const float*)d_in[28];
    const float* be3   = (const float*)d_in[29];
    float* out = (float*)d_out;

    float *p_ln, *p_x1, *p_xin, *p_mt, *p_x2, *p_xpp, *p_pp, *p_qkvb;
    __half *p_lnh,*p_lnl,*p_qkvh,*p_qkvl,*p_aoh,*p_aol,*p_xch,*p_xcl,*p_yh,*p_yl,*p_ffh,*p_ffl;
    __half *p_wqkvh,*p_wqkvl,*p_woh,*p_wol;
    __half *p_inh,*p_inl,*p_xph,*p_xpl,*p_oth,*p_otl,*p_f1h,*p_f1l,*p_f2h,*p_f2l;
    cudaGetSymbolAddress((void**)&p_ln,   g_ln);
    cudaGetSymbolAddress((void**)&p_x1,   g_x1);
    cudaGetSymbolAddress((void**)&p_xin,  g_xin);
    cudaGetSymbolAddress((void**)&p_mt,   g_mt);
    cudaGetSymbolAddress((void**)&p_x2,   g_x2);
    cudaGetSymbolAddress((void**)&p_xpp,  g_xpp);
    cudaGetSymbolAddress((void**)&p_pp,   g_pp);
    cudaGetSymbolAddress((void**)&p_qkvb, g_qkvb);
    cudaGetSymbolAddress((void**)&p_lnh, g_lnh); cudaGetSymbolAddress((void**)&p_lnl, g_lnl);
    cudaGetSymbolAddress((void**)&p_qkvh, g_qkvh); cudaGetSymbolAddress((void**)&p_qkvl, g_qkvl);
    cudaGetSymbolAddress((void**)&p_aoh, g_aoh); cudaGetSymbolAddress((void**)&p_aol, g_aol);
    cudaGetSymbolAddress((void**)&p_xch, g_xch); cudaGetSymbolAddress((void**)&p_xcl, g_xcl);
    cudaGetSymbolAddress((void**)&p_yh,  g_yh);  cudaGetSymbolAddress((void**)&p_yl,  g_yl);
    cudaGetSymbolAddress((void**)&p_ffh, g_ffh); cudaGetSymbolAddress((void**)&p_ffl, g_ffl);
    cudaGetSymbolAddress((void**)&p_wqkvh, g_wqkvh); cudaGetSymbolAddress((void**)&p_wqkvl, g_wqkvl);
    cudaGetSymbolAddress((void**)&p_woh, g_woh); cudaGetSymbolAddress((void**)&p_wol, g_wol);
    cudaGetSymbolAddress((void**)&p_inh, g_inh); cudaGetSymbolAddress((void**)&p_inl, g_inl);
    cudaGetSymbolAddress((void**)&p_xph, g_xph); cudaGetSymbolAddress((void**)&p_xpl, g_xpl);
    cudaGetSymbolAddress((void**)&p_oth, g_oth); cudaGetSymbolAddress((void**)&p_otl, g_otl);
    cudaGetSymbolAddress((void**)&p_f1h, g_f1h); cudaGetSymbolAddress((void**)&p_f1l, g_f1l);
    cudaGetSymbolAddress((void**)&p_f2h, g_f2h); cudaGetSymbolAddress((void**)&p_f2l, g_f2l);

    cudaFuncSetAttribute(gemm2<0,false,false>, cudaFuncAttributeMaxDynamicSharedMemorySize, GEMM_SMEM);
    cudaFuncSetAttribute(gemm2<1,false,false>, cudaFuncAttributeMaxDynamicSharedMemorySize, GEMM_SMEM);
    cudaFuncSetAttribute(gemm2<1,true,false>,  cudaFuncAttributeMaxDynamicSharedMemorySize, GEMM_SMEM);
    cudaFuncSetAttribute(gemm2<2,false,false>, cudaFuncAttributeMaxDynamicSharedMemorySize, GEMM_SMEM);
    cudaFuncSetAttribute(attn_k, cudaFuncAttributeMaxDynamicSharedMemorySize, ATTN_SMEM);

    // --- weight pre-split (deterministic each call) ---
    wsplit_k<<<(DM*DM+255)/256, 256>>>(Wq,   p_wqkvh,           p_wqkvl,           DM,  DM,  DM);
    wsplit_k<<<(DM*DM+255)/256, 256>>>(Wk,   p_wqkvh + DM*DM,   p_wqkvl + DM*DM,   DM,  DM,  DM);
    wsplit_k<<<(DM*DM+255)/256, 256>>>(Wv,   p_wqkvh + 2*DM*DM, p_wqkvl + 2*DM*DM, DM,  DM,  DM);
    catb_k<<<(3*DM+255)/256, 256>>>(bq, bk, bv);
    wsplit_k<<<(DM*DM+255)/256, 256>>>(Wo,   p_woh, p_wol, DM,  DM,  DM);
    wsplit_k<<<(DIN*DM+255)/256, 256>>>(inw, p_inh, p_inl, DIN, DM,  DIN);
    wsplit_k<<<(128*DIN+255)/256, 256>>>(xpw,p_xph, p_xpl, XPN, DIN, 128);
    wsplit_k<<<(DM*DIN+255)/256, 256>>>(outw,p_oth, p_otl, DM,  DIN, DM);
    wsplit_k<<<(DFF*DM+255)/256, 256>>>(fc1w,p_f1h, p_f1l, DFF, DM,  DFF);
    wsplit_k<<<(DM*DFF+255)/256, 256>>>(fc2w,p_f2h, p_f2l, DM,  DFF, DM);

    // --- block 1: attention ---
    ln_k<true,false,false,true><<<SEQ, 256>>>(x, g1, be1, nullptr, nullptr, p_lnh, p_lnl);
    gemm2<1,false,false><<<dim3(24,16), 256, GEMM_SMEM>>>(p_lnh,p_lnl, p_wqkvh,p_wqkvl, p_qkvb, nullptr, nullptr, p_qkvh,p_qkvl, SEQ, 3*DM, DM);
    attn_k<<<dim3(SEQ/64, NH), 128, ATTN_SMEM>>>(p_qkvh, p_qkvl, p_aoh, p_aol);
    gemm2<2,false,false><<<dim3(8,16,2), 256, GEMM_SMEM>>>(p_aoh,p_aol, p_woh,p_wol, nullptr, nullptr, p_pp, nullptr,nullptr, SEQ, DM, DM);
    reduce2_k<true><<<(SEQ*DM+255)/256, 256>>>(p_pp, bo, x, p_x1);

    // --- block 2: mamba ---
    ln_k<true,false,true,false><<<SEQ, 256>>>(p_x1, g2, be2, nullptr, p_ln, nullptr, nullptr);
    ln_k<false,false,false,true><<<SEQ, 256>>>(p_ln, nullptr, nullptr, nullptr, nullptr, p_lnh, p_lnl);
    gemm2<0,false,false><<<dim3(16,16), 256, GEMM_SMEM>>>(p_lnh,p_lnl, p_inh,p_inl, inb, nullptr, p_xin, nullptr,nullptr, SEQ, DIN, DM);
    conv_k<<<SEQ*DIN/256, 256>>>(convw, convb);
    gemm2<2,false,false><<<dim3(1,16,KSPL), 256, GEMM_SMEM>>>(p_xch,p_xcl, p_xph,p_xpl, nullptr, nullptr, p_xpp, nullptr,nullptr, SEQ, 128, DIN);
    reduce_xp<<<(SEQ*XPN+255)/256, 256>>>(xpb);
    bc_k<<<SEQ, 32>>>();
    buildM_k<<<1, 256>>>(Amat);
    scan_k<<<1, 1024>>>();
    y_k<<<SEQ*DIN/256, 256>>>(Dp);
    gemm2<2,false,false><<<dim3(8,16,2), 256, GEMM_SMEM>>>(p_yh,p_yl, p_oth,p_otl, nullptr, nullptr, p_pp, nullptr,nullptr, SEQ, DM, DIN);
    reduce2_k<false><<<(SEQ*DM+255)/256, 256>>>(p_pp, outb, nullptr, p_mt);
    ln_k<false,true,true,false><<<SEQ, 256>>>(p_mt, nullptr, nullptr, p_x1, p_x2, nullptr, nullptr);

    // --- block 3: FFN ---
    ln_k<true,false,false,true><<<SEQ, 256>>>(p_x2, g3, be3, nullptr, nullptr, p_lnh, p_lnl);
    gemm2<1,true,false><<<dim3(32,16), 256, GEMM_SMEM>>>(p_lnh,p_lnl, p_f1h,p_f1l, fc1b, nullptr, nullptr, p_ffh,p_ffl, SEQ, DFF, DM);
    gemm2<2,false,false><<<dim3(8,16,2), 256, GEMM_SMEM>>>(p_ffh,p_ffl, p_f2h,p_f2l, nullptr, nullptr, p_pp, nullptr,nullptr, SEQ, DM, DFF);
    reduce2_k<true><<<(SEQ*DM+255)/256, 256>>>(p_pp, fc2b, p_x2, out);
}